// round 3
// baseline (speedup 1.0000x reference)
#include <cuda_runtime.h>

#define NTOK 4096
#define DIM  512
#define H    12
#define ZD   64
#define HZ   768
#define RPV  36
#define CPV  20
#define SP   18

typedef unsigned long long u64;

__device__ float g_Qp[NTOK*HZ];
__device__ float g_Kp[NTOK*HZ];
__device__ float g_dQ[NTOK*HZ];
__device__ float g_dK[NTOK*HZ];
__device__ float g_LSE[NTOK*H];
__device__ double g_part[64];

__device__ __forceinline__ u64 pk(float lo, float hi){
    u64 r; asm("mov.b64 %0, {%1,%2};" : "=l"(r) : "f"(lo), "f"(hi)); return r;
}
__device__ __forceinline__ u64 splat2(float x){ return pk(x,x); }
__device__ __forceinline__ void fma2(u64 &d, u64 a, u64 b){
    asm("fma.rn.f32x2 %0, %1, %2, %0;" : "+l"(d) : "l"(a), "l"(b));
}
__device__ __forceinline__ float2 unpk(u64 v){
    float2 r; asm("mov.b64 {%0,%1}, %2;" : "=f"(r.x), "=f"(r.y) : "l"(v)); return r;
}

__device__ __forceinline__ float fexp(float x){
    x = fminf(fmaxf(x,-87.f),87.f);
    float n = rintf(x*1.4426950408889634f);
    float g = fmaf(n,-0.69314718055994531f,x);
    float p = 1.3888889e-3f;
    p = fmaf(p,g,8.3333333e-3f);
    p = fmaf(p,g,4.1666667e-2f);
    p = fmaf(p,g,1.6666667e-1f);
    p = fmaf(p,g,0.5f);
    p = fmaf(p,g,1.f);
    p = fmaf(p,g,1.f);
    return p*__int_as_float(((int)n+127)<<23);
}

// out[n,hz] = sum_d A[n,d]*W[hz,d] + B[hz]
__global__ void __launch_bounds__(256) proj_kernel(const float* __restrict__ A,
                                                   const float* __restrict__ W,
                                                   const float* __restrict__ Bv,
                                                   int sel){
    float* out = sel ? g_Kp : g_Qp;
    __shared__ float As[16][68];
    __shared__ float Ws[16][68];
    const int tid = threadIdx.x;
    const int tx = tid & 15, ty = tid >> 4;
    const int n0 = blockIdx.y*64, j0 = blockIdx.x*64;
    const int lr = tid >> 2, lc = (tid & 3) << 2;
    float acc[4][4] = {};
    for(int d0 = 0; d0 < DIM; d0 += 16){
        float4 va = *(const float4*)&A[(n0+lr)*DIM + d0 + lc];
        float4 vw = *(const float4*)&W[(j0+lr)*DIM + d0 + lc];
        __syncthreads();
        As[lc+0][lr]=va.x; As[lc+1][lr]=va.y; As[lc+2][lr]=va.z; As[lc+3][lr]=va.w;
        Ws[lc+0][lr]=vw.x; Ws[lc+1][lr]=vw.y; Ws[lc+2][lr]=vw.z; Ws[lc+3][lr]=vw.w;
        __syncthreads();
#pragma unroll
        for(int kd = 0; kd < 16; kd++){
            float av[4], bv[4];
#pragma unroll
            for(int i=0;i<4;i++) av[i]=As[kd][ty*4+i];
#pragma unroll
            for(int j=0;j<4;j++) bv[j]=Ws[kd][tx*4+j];
#pragma unroll
            for(int i=0;i<4;i++)
#pragma unroll
                for(int j=0;j<4;j++) acc[i][j]=fmaf(av[i],bv[j],acc[i][j]);
        }
    }
#pragma unroll
    for(int i=0;i<4;i++)
#pragma unroll
        for(int j=0;j<4;j++)
            out[(n0+ty*4+i)*HZ + j0+tx*4+j] = acc[i][j] + Bv[j0+tx*4+j];
}

// MODE 0: forward LSE.  MODE 1: dQ (rows=q).  MODE 2: dK (rows=k).
template<int MODE>
__global__ void __launch_bounds__(384) pass_kernel(const float* __restrict__ adj,
                                                   const float* __restrict__ Hw,
                                                   const float* __restrict__ betas){
    extern __shared__ float sm[];
    float* Rt = sm;                  // [HZ][RPV]
    float* Ct = Rt + HZ*RPV;         // [HZ][CPV]
    float* ss = Ct + HZ*CPV;         // [H][32][SP]
    float* base = ss + H*32*SP;
    float* psb  = base;              // [H][32][SP] (bwd only)
    float* adjs = (MODE==0) ? base : base + H*32*SP;  // [32][17]
    float* lses = adjs + 32*17;      // [16][H] (MODE 2)

    const int tid = threadIdx.x;
    const int w = tid >> 5, l = tid & 31;
    const int rb = blockIdx.x * 32;
    const float* Rg = (MODE==2) ? g_Kp : g_Qp;
    const float* Cg = (MODE==2) ? g_Qp : g_Kp;

    u64 C2s[H], D2s[H];
    const float bw = betas[w];
#pragma unroll
    for(int h=0; h<H; h++){
        C2s[h] = splat2(betas[h]*Hw[h*H + w]);
        if(MODE) D2s[h] = splat2(bw*Hw[w*H + h]*(-1.f/betas[h]));
    }
    float lse_reg = 0.f;
    if(MODE==1) lse_reg = g_LSE[(rb+l)*H + w];

    for(int idx = tid; idx < 32*192; idx += 384){
        int r = idx/192, c4 = (idx%192)<<2;
        float4 v = *(const float4*)&Rg[(rb+r)*HZ + c4];
        Rt[(c4+0)*RPV+r]=v.x; Rt[(c4+1)*RPV+r]=v.y; Rt[(c4+2)*RPV+r]=v.z; Rt[(c4+3)*RPV+r]=v.w;
    }

    const int rg=l>>2, sub=l&3, r0=rg<<2, c0=sub<<2, z0=sub<<4;
    float m = -1e30f, lsum = 0.f;
    u64 dacc2[4][8] = {};

    for(int cc = 0; cc < NTOK; cc += 16){
        __syncthreads();
        for(int idx = tid; idx < 16*192; idx += 384){
            int c = idx/192, c4 = (idx%192)<<2;
            float4 v = *(const float4*)&Cg[(cc+c)*HZ + c4];
            Ct[(c4+0)*CPV+c]=v.x; Ct[(c4+1)*CPV+c]=v.y; Ct[(c4+2)*CPV+c]=v.z; Ct[(c4+3)*CPV+c]=v.w;
        }
        if(MODE==2){
            for(int idx = tid; idx < 512; idx += 384){
                int c = idx>>5, kk = idx&31;
                adjs[kk*17 + c] = adj[(cc+c)*NTOK + rb + kk];
            }
            for(int idx = tid; idx < 16*H; idx += 384)
                lses[idx] = g_LSE[(cc + idx/H)*H + (idx%H)];
        } else {
            for(int idx = tid; idx < 512; idx += 384){
                int q = idx>>4, k = idx&15;
                adjs[q*17 + k] = adj[(rb+q)*NTOK + cc + k];
            }
        }
        __syncthreads();

        // scores: warp w = head, 4r x 4c per thread, packed along c
        u64 acc01[4] = {}, acc23[4] = {};
#pragma unroll 8
        for(int z = 0; z < ZD; z++){
            int hz = w*ZD + z;
            const float4 a4 = *(const float4*)&Rt[hz*RPV + r0];
            const float4 b4 = *(const float4*)&Ct[hz*CPV + c0];
            u64 b01 = pk(b4.x, b4.y), b23 = pk(b4.z, b4.w);
            u64 s;
            s = splat2(a4.x); fma2(acc01[0], s, b01); fma2(acc23[0], s, b23);
            s = splat2(a4.y); fma2(acc01[1], s, b01); fma2(acc23[1], s, b23);
            s = splat2(a4.z); fma2(acc01[2], s, b01); fma2(acc23[2], s, b23);
            s = splat2(a4.w); fma2(acc01[3], s, b01); fma2(acc23[3], s, b23);
        }
#pragma unroll
        for(int i=0;i<4;i++){
            *(u64*)&ss[(w*32 + r0+i)*SP + c0]     = acc01[i];
            *(u64*)&ss[(w*32 + r0+i)*SP + c0 + 2] = acc23[i];
        }
        __syncthreads();

        // mix: warp w = hp, lane l = row, packed along k pairs
#pragma unroll
        for(int kp = 0; kp < 8; kp++){
            const int k = kp << 1;
            u64 a2 = 0;
#pragma unroll
            for(int h=0; h<H; h++)
                fma2(a2, C2s[h], *(const u64*)&ss[(h*32+l)*SP + k]);
            float2 av = unpk(a2);
            float ad0 = adjs[l*17 + k], ad1 = adjs[l*17 + k + 1];
            if(MODE==0){
                if(ad0 != 0.f){
                    if(av.x <= m) lsum += fexp(av.x - m);
                    else { lsum = fmaf(lsum, fexp(m - av.x), 1.f); m = av.x; }
                }
                if(ad1 != 0.f){
                    if(av.y <= m) lsum += fexp(av.y - m);
                    else { lsum = fmaf(lsum, fexp(m - av.y), 1.f); m = av.y; }
                }
            } else {
                float lse0, lse1;
                if(MODE==1){ lse0 = lse_reg; lse1 = lse_reg; }
                else { lse0 = lses[k*H + w]; lse1 = lses[(k+1)*H + w]; }
                float p0 = (ad0 != 0.f) ? fexp(av.x - lse0) : 0.f;
                float p1 = (ad1 != 0.f) ? fexp(av.y - lse1) : 0.f;
                *(u64*)&psb[(w*32+l)*SP + k] = pk(p0, p1);
            }
        }
        if(MODE){
            __syncthreads();
#pragma unroll
            for(int kp = 0; kp < 8; kp++){
                const int k = kp << 1;
                u64 s2 = 0;
#pragma unroll
                for(int hp=0; hp<H; hp++)
                    fma2(s2, D2s[hp], *(const u64*)&psb[(hp*32+l)*SP + k]);
                *(u64*)&ss[(w*32+l)*SP + k] = s2;
            }
            __syncwarp();
            // dacc: warp w = head, 4r x 16z per thread, packed along z pairs
#pragma unroll 4
            for(int k = 0; k < 16; k++){
                u64 w2s[4];
#pragma unroll
                for(int i=0;i<4;i++) w2s[i] = splat2(ss[(w*32 + r0+i)*SP + k]);
#pragma unroll
                for(int zp=0; zp<8; zp++){
                    const int zi = zp << 1;
                    float cv0 = Ct[(w*ZD + z0 + zi)*CPV + k];
                    float cv1 = Ct[(w*ZD + z0 + zi + 1)*CPV + k];
                    u64 c2 = pk(cv0, cv1);
                    fma2(dacc2[0][zp], w2s[0], c2);
                    fma2(dacc2[1][zp], w2s[1], c2);
                    fma2(dacc2[2][zp], w2s[2], c2);
                    fma2(dacc2[3][zp], w2s[3], c2);
                }
            }
        }
    }

    if(MODE==0){
        float lse = (lsum > 0.f) ? (m + logf(lsum)) : 0.f;
        g_LSE[(rb+l)*H + w] = lse;
    } else {
        float* dst = (MODE==1) ? g_dQ : g_dK;
#pragma unroll
        for(int i=0;i<4;i++){
            float* p = &dst[(rb + r0 + i)*HZ + w*ZD + z0];
#pragma unroll
            for(int zp=0; zp<8; zp+=2){
                float2 v0 = unpk(dacc2[i][zp]);
                float2 v1 = unpk(dacc2[i][zp+1]);
                *(float4*)&p[zp<<1] = make_float4(v0.x, v0.y, v1.x, v1.y);
            }
        }
    }
}

__global__ void energy1_kernel(const float* __restrict__ betas){
    __shared__ double red[256];
    const int tid = threadIdx.x;
    const int base = blockIdx.x * 768;
    double a = 0.0;
    for(int i = tid; i < 768; i += 256){
        int idx = base + i;
        a += (double)g_LSE[idx] * (-1.0/(double)betas[idx % H]);
    }
    red[tid] = a;
    __syncthreads();
    for(int s = 128; s > 0; s >>= 1){
        if(tid < s) red[tid] += red[tid + s];
        __syncthreads();
    }
    if(tid == 0) g_part[blockIdx.x] = red[0];
}

__global__ void energy2_kernel(float* __restrict__ out){
    __shared__ double red[64];
    const int tid = threadIdx.x;
    red[tid] = g_part[tid];
    __syncthreads();
    for(int s = 32; s > 0; s >>= 1){
        if(tid < s) red[tid] += red[tid + s];
        __syncthreads();
    }
    if(tid == 0) out[0] = (float)red[0];
}

// dG[n,d] = sum_hz dQ[n,hz]*Wq[hz,d] + dK[n,hz]*Wk[hz,d]
__global__ void __launch_bounds__(256) grad_kernel(const float* __restrict__ Wq,
                                                   const float* __restrict__ Wk,
                                                   float* __restrict__ out){
    __shared__ float Aq[16][68], Ak[16][68], Bq[16][68], Bk[16][68];
    const int tid = threadIdx.x;
    const int n0 = blockIdx.y*64, d0 = blockIdx.x*64;
    const int tx = tid & 15, ty = tid >> 4;
    const int lr = tid >> 2, lc = (tid & 3) << 2;
    const int wr = tid >> 4, wc = (tid & 15) << 2;
    float acc[4][4] = {};
    for(int h0 = 0; h0 < HZ; h0 += 16){
        float4 va = *(const float4*)&g_dQ[(n0+lr)*HZ + h0 + lc];
        float4 vk = *(const float4*)&g_dK[(n0+lr)*HZ + h0 + lc];
        float4 wq = *(const float4*)&Wq[(h0+wr)*DIM + d0 + wc];
        float4 wk = *(const float4*)&Wk[(h0+wr)*DIM + d0 + wc];
        __syncthreads();
        Aq[lc+0][lr]=va.x; Aq[lc+1][lr]=va.y; Aq[lc+2][lr]=va.z; Aq[lc+3][lr]=va.w;
        Ak[lc+0][lr]=vk.x; Ak[lc+1][lr]=vk.y; Ak[lc+2][lr]=vk.z; Ak[lc+3][lr]=vk.w;
        *(float4*)&Bq[wr][wc] = wq;
        *(float4*)&Bk[wr][wc] = wk;
        __syncthreads();
#pragma unroll
        for(int kd = 0; kd < 16; kd++){
            float aq[4], ak[4], bq[4], bk[4];
#pragma unroll
            for(int i=0;i<4;i++){ aq[i]=Aq[kd][ty*4+i]; ak[i]=Ak[kd][ty*4+i]; }
#pragma unroll
            for(int j=0;j<4;j++){ bq[j]=Bq[kd][tx*4+j]; bk[j]=Bk[kd][tx*4+j]; }
#pragma unroll
            for(int i=0;i<4;i++)
#pragma unroll
                for(int j=0;j<4;j++){
                    acc[i][j]=fmaf(aq[i],bq[j],acc[i][j]);
                    acc[i][j]=fmaf(ak[i],bk[j],acc[i][j]);
                }
        }
    }
#pragma unroll
    for(int i=0;i<4;i++)
#pragma unroll
        for(int j=0;j<4;j++)
            out[1 + (n0+ty*4+i)*DIM + d0+tx*4+j] = acc[i][j];
}

extern "C" void kernel_launch(void* const* d_in, const int* in_sizes, int n_in,
                              void* d_out, int out_size){
    const float* g    = (const float*)d_in[0];
    const float* adj  = (const float*)d_in[1];
    const float* Wk   = (const float*)d_in[2];
    const float* Wq   = (const float*)d_in[3];
    const float* Hw   = (const float*)d_in[4];
    const float* Bk   = (const float*)d_in[5];
    const float* Bq   = (const float*)d_in[6];
    const float* betas= (const float*)d_in[7];
    float* out = (float*)d_out;

    const int SM0 = (HZ*RPV + HZ*CPV + H*32*SP + 32*17) * 4;
    const int SM1 = SM0 + H*32*SP*4;
    const int SM2 = SM1 + 16*H*4;
    cudaFuncSetAttribute(pass_kernel<0>, cudaFuncAttributeMaxDynamicSharedMemorySize, SM0);
    cudaFuncSetAttribute(pass_kernel<1>, cudaFuncAttributeMaxDynamicSharedMemorySize, SM1);
    cudaFuncSetAttribute(pass_kernel<2>, cudaFuncAttributeMaxDynamicSharedMemorySize, SM2);

    proj_kernel<<<dim3(HZ/64, NTOK/64), 256>>>(g, Wq, Bq, 0);
    proj_kernel<<<dim3(HZ/64, NTOK/64), 256>>>(g, Wk, Bk, 1);
    pass_kernel<0><<<NTOK/32, 384, SM0>>>(adj, Hw, betas);
    energy1_kernel<<<64, 256>>>(betas);
    energy2_kernel<<<1, 64>>>(out);
    pass_kernel<1><<<NTOK/32, 384, SM1>>>(adj, Hw, betas);
    pass_kernel<2><<<NTOK/32, 384, SM2>>>(adj, Hw, betas);
    grad_kernel<<<dim3(DIM/64, NTOK/64), 256>>>(Wq, Wk, out);
}